// round 17
// baseline (speedup 1.0000x reference)
#include <cuda_runtime.h>
#include <cuda_fp16.h>
#include <math.h>
#include <stdint.h>

#define B_  512
#define XD  768
#define YD  128
#define H2_ 512
#define NPART 16
#define KS1 4          // gemm1 K-split (768/4 = 192)
#define KS2 8          // gemm2 K-split (512/8 = 64)
#define APITCH 33

__device__ float  g_H[2][KS1][B_ * H2_];   // gemm1 raw partials
__device__ float  g_Q[2][KS2][B_ * YD];    // gemm2 raw partials
__device__ double g_SyP [NPART][YD];
__device__ double g_Sy2P[NPART][YD];
__device__ double g_pos_row[B_];
__device__ double g_all_row[B_];
__device__ unsigned g_mt_ctr[8] = {};
__device__ unsigned g_ctr = 0;

// ---------------- fp16 2-term split (Markidis): x = h + l ----------------
__device__ __forceinline__ void split_pack(float x0, float x1,
                                           uint32_t &hi, uint32_t &lo) {
    __half h0 = __float2half_rn(x0), h1 = __float2half_rn(x1);
    float r0 = x0 - __half2float(h0), r1 = x1 - __half2float(h1);
    __half l0 = __float2half_rn(r0), l1 = __float2half_rn(r1);
    __half2 H = __halves2half2(h0, h1), L = __halves2half2(l0, l1);
    hi = *(uint32_t*)&H; lo = *(uint32_t*)&L;
}

#define MMA16(c, A, B) \
    asm volatile("mma.sync.aligned.m16n8k16.row.col.f32.f16.f16.f32 " \
        "{%0,%1,%2,%3},{%4,%5,%6,%7},{%8,%9},{%0,%1,%2,%3};" \
        : "+f"((c)[0]), "+f"((c)[1]), "+f"((c)[2]), "+f"((c)[3]) \
        : "r"((A)[0]), "r"((A)[1]), "r"((A)[2]), "r"((A)[3]), \
          "r"((B)[0]), "r"((B)[1]))

// ---------------------------------------------------------------------------
// Kernel A (R16-proven): blocks 0..127 = GEMM1 partials via 3x-fp16 HMMA,
// 1024 thr, 32 warps (8M x 4N, warp tile 16x32), 128x128 tile, K=192 slice.
// blocks 128..143 = y column stats.
// ---------------------------------------------------------------------------
__global__ __launch_bounds__(1024) void k_gemm1_mma(
    const float* __restrict__ X, const float* __restrict__ Y,
    const float* __restrict__ Wmu, const float* __restrict__ Wlv)
{
    const int b = blockIdx.x;
    if (b >= 128) {
        const int p = b - 128;
        const int d = threadIdx.x;
        if (d < YD) {
            const int j0 = p * (B_ / NPART);
            double sy0 = 0, sy1 = 0, s20 = 0, s21 = 0;
            #pragma unroll 4
            for (int j = j0; j < j0 + B_ / NPART; j += 2) {
                double v0 = (double)Y[j * YD + d], v1 = (double)Y[(j + 1) * YD + d];
                sy0 += v0; s20 = fma(v0, v0, s20);
                sy1 += v1; s21 = fma(v1, v1, s21);
            }
            g_SyP[p][d] = sy0 + sy1; g_Sy2P[p][d] = s20 + s21;
        }
        return;
    }

    __shared__ uint32_t Ah[2 * 8 * 4 * APITCH], Al[2 * 8 * 4 * APITCH];
    __shared__ uint32_t Bh[2 * 16 * 2 * APITCH], Bl[2 * 16 * 2 * APITCH];

    const int head = b & 1;
    const int ks   = (b >> 1) & 3;
    const int t4   = b >> 3;
    const int m0   = (t4 >> 2) * 128;
    const int n0   = (t4 & 3) * 128;
    const int kb   = ks * 192;
    const float* W = head ? Wlv : Wmu;
    float* P       = &g_H[head][ks][0];

    const int tid  = threadIdx.x;
    const int wid  = tid >> 5,  lane = tid & 31;
    const int wm   = wid >> 2,  wn   = wid & 3;   // wm 0..7, wn 0..3
    const int lg   = lane >> 2, lt   = lane & 3;

    const int ar = tid >> 3, ap = tid & 7;
    const int a_mt   = ar >> 4;
    const int a_slot = ((ar >> 3) & 1) + 2 * (ap >> 2);
    const int a_lane = 4 * (ar & 7) + (ap & 3);
    const float* Xp = X + (size_t)(m0 + ar) * XD + kb + ap * 2;
    const int bn = tid & 127, bkp = tid >> 7;
    const int b_lt = bkp & 3, b_slot = bkp >> 2;
    const int b_nt = bn >> 3;
    const int b_pl = 4 * (bn & 7) + b_lt;
    const float* Wp = W + (size_t)(kb + 2 * bkp) * H2_ + n0 + bn;

    float acc[4][4] = {};
    float2 xa2; float wv0, wv1;

    #define G1_LOAD(ch) do { \
        xa2 = *(const float2*)(Xp + (ch) * 16); \
        wv0 = Wp[(size_t)(ch) * 16 * H2_]; \
        wv1 = Wp[(size_t)(ch) * 16 * H2_ + H2_]; \
    } while (0)

    #define G1_STAGE(bf) do { \
        uint32_t ah, al; \
        split_pack(xa2.x, xa2.y, ah, al); \
        int ai = (((bf) * 8 + a_mt) * 4 + a_slot) * APITCH + a_lane; \
        Ah[ai] = ah; Al[ai] = al; \
        uint32_t bhv, blv; \
        split_pack(wv0, wv1, bhv, blv); \
        int bi = (((bf) * 16 + b_nt) * 2 + b_slot) * APITCH + b_pl; \
        Bh[bi] = bhv; Bl[bi] = blv; \
    } while (0)

    G1_LOAD(0);
    G1_STAGE(0);
    G1_LOAD(1);
    __syncthreads();

    for (int ch = 0; ch < 12; ch++) {
        const int bfc = ch & 1;
        if (ch + 1 < 12) G1_STAGE((ch + 1) & 1);
        if (ch + 2 < 12) G1_LOAD(ch + 2);

        uint32_t Af[4], Afl[4];
        {
            int base = ((bfc * 8 + wm) * 4) * APITCH + lane;
            #pragma unroll
            for (int s = 0; s < 4; s++) {
                Af [s] = Ah[base + s * APITCH];
                Afl[s] = Al[base + s * APITCH];
            }
        }
        uint32_t Bf[4][2], Bfl[4][2];
        #pragma unroll
        for (int nf = 0; nf < 4; nf++) {
            int nt = wn * 4 + nf;
            int base = ((bfc * 16 + nt) * 2) * APITCH + lane;
            #pragma unroll
            for (int s = 0; s < 2; s++) {
                Bf [nf][s] = Bh[base + s * APITCH];
                Bfl[nf][s] = Bl[base + s * APITCH];
            }
        }
        #pragma unroll
        for (int nf = 0; nf < 4; nf++) {
            MMA16(acc[nf], Af,  Bf[nf]);
            MMA16(acc[nf], Af,  Bfl[nf]);
            MMA16(acc[nf], Afl, Bf[nf]);
        }
        __syncthreads();
    }

    {
        int row0 = m0 + wm * 16 + lg;
        #pragma unroll
        for (int nf = 0; nf < 4; nf++) {
            int col = n0 + wn * 32 + nf * 8 + lt * 2;
            *(float2*)(P + (size_t)row0 * H2_ + col)       = make_float2(acc[nf][0], acc[nf][1]);
            *(float2*)(P + (size_t)(row0 + 8) * H2_ + col) = make_float2(acc[nf][2], acc[nf][3]);
        }
    }
}

// ---------------------------------------------------------------------------
// Kernel B: GEMM2 (R11-proven core) + FUSED rows/final via last-arriver
// tickets. grid 128 = 2 heads x 8 M(64) x 8 K. After the partial store, the
// 16th block of each mtile does the rows for its 64 rows; the 8th mtile
// finisher does the deterministic 512-row final reduce.
// ---------------------------------------------------------------------------
__global__ __launch_bounds__(256) void k_gemm2_rows(
    const float* __restrict__ b1mu, const float* __restrict__ b1lv,
    const float* __restrict__ W2mu, const float* __restrict__ W2lv,
    const float* __restrict__ Y,
    const float* __restrict__ b2mu, const float* __restrict__ b2lv,
    float* __restrict__ out, int out_size)
{
    __shared__ __align__(16) uint32_t SM[6336];   // 25KB pool
    uint32_t* Ah = SM;                  // 1056
    uint32_t* Al = SM + 1056;           // 1056
    uint32_t* Bh = SM + 2112;           // 2112
    uint32_t* Bl = SM + 4224;           // 2112
    __shared__ bool s_mt_last, s_last;

    const int b    = blockIdx.x;
    const int head = b & 1;
    const int ks   = (b >> 1) & 7;
    const int mt   = b >> 4;            // 0..7
    const int m0   = mt * 64;
    const int kb   = ks * 64;
    const float* Hb = &g_H[head][0][0];
    const float* b1 = head ? b1lv : b1mu;
    const float* W  = head ? W2lv : W2mu;
    float*       Q  = g_Q[head][ks];
    const size_t HS = (size_t)B_ * H2_;

    const int tid  = threadIdx.x;
    const int wid  = tid >> 5,  lane = tid & 31;
    const int wm   = wid >> 2,  wn   = wid & 3;
    const int lg   = lane >> 2, lt   = lane & 3;

    const int ar = tid >> 2, akq = tid & 3;
    const int a_mt   = ar >> 4;
    const int a_slot = ((ar >> 3) & 1) + 2 * (akq >> 1);
    const int a_lane = 4 * (ar & 7) + 2 * (akq & 1);
    const size_t aoff = (size_t)(m0 + ar) * H2_ + kb + akq * 4;
    const int bkp = tid >> 5, bn2b = tid & 31;
    const int b_lt = bkp & 3, b_slot = bkp >> 2;
    const float* Wp = W + (size_t)(kb + 2 * bkp) * YD;

    float acc[2][4][4] = {};
    float4 hh0, hh1, hh2, hh3, bv4;
    float2 wu0[2], wu1[2];

    #define G2_LOAD(ch) do { \
        hh0 = *(const float4*)(Hb + 0 * HS + aoff + (ch) * 16); \
        hh1 = *(const float4*)(Hb + 1 * HS + aoff + (ch) * 16); \
        hh2 = *(const float4*)(Hb + 2 * HS + aoff + (ch) * 16); \
        hh3 = *(const float4*)(Hb + 3 * HS + aoff + (ch) * 16); \
        bv4 = *(const float4*)(b1 + kb + akq * 4 + (ch) * 16); \
        _Pragma("unroll") \
        for (int u = 0; u < 2; u++) { \
            int n = 2 * (bn2b + 32 * u); \
            wu0[u] = *(const float2*)(Wp + (size_t)(ch) * 16 * YD + n); \
            wu1[u] = *(const float2*)(Wp + (size_t)(ch) * 16 * YD + YD + n); \
        } \
    } while (0)

    #define G2_STAGE(bf) do { \
        float e0 = fmaxf(hh0.x + hh1.x + hh2.x + hh3.x + bv4.x, 0.0f); \
        float e1 = fmaxf(hh0.y + hh1.y + hh2.y + hh3.y + bv4.y, 0.0f); \
        float e2 = fmaxf(hh0.z + hh1.z + hh2.z + hh3.z + bv4.z, 0.0f); \
        float e3 = fmaxf(hh0.w + hh1.w + hh2.w + hh3.w + bv4.w, 0.0f); \
        uint32_t h01, l01, h23, l23; \
        split_pack(e0, e1, h01, l01); \
        split_pack(e2, e3, h23, l23); \
        int ai = (((bf) * 4 + a_mt) * 4 + a_slot) * APITCH + a_lane; \
        Ah[ai] = h01; Ah[ai + 1] = h23; \
        Al[ai] = l01; Al[ai + 1] = l23; \
        _Pragma("unroll") \
        for (int u = 0; u < 2; u++) { \
            _Pragma("unroll") \
            for (int j = 0; j < 2; j++) { \
                int n = 2 * (bn2b + 32 * u) + j; \
                int nt = n >> 3; \
                float vk0 = j ? wu0[u].y : wu0[u].x; \
                float vk1 = j ? wu1[u].y : wu1[u].x; \
                uint32_t bhv, blv; \
                split_pack(vk0, vk1, bhv, blv); \
                int bi = (((bf) * 16 + nt) * 2 + b_slot) * APITCH + 4 * (n & 7) + b_lt; \
                Bh[bi] = bhv; Bl[bi] = blv; \
            } \
        } \
    } while (0)

    G2_LOAD(0);
    G2_STAGE(0);
    G2_LOAD(1);
    __syncthreads();

    for (int ch = 0; ch < 4; ch++) {
        const int bfc = ch & 1;
        if (ch + 1 < 4) G2_STAGE((ch + 1) & 1);
        if (ch + 2 < 4) G2_LOAD(ch + 2);

        uint32_t Af[2][4], Afl[2][4];
        #pragma unroll
        for (int mf = 0; mf < 2; mf++) {
            int mtt = wm * 2 + mf;
            int base = ((bfc * 4 + mtt) * 4) * APITCH + lane;
            #pragma unroll
            for (int s = 0; s < 4; s++) {
                Af [mf][s] = Ah[base + s * APITCH];
                Afl[mf][s] = Al[base + s * APITCH];
            }
        }
        uint32_t Bf[4][2], Bfl[4][2];
        #pragma unroll
        for (int nf = 0; nf < 4; nf++) {
            int nt = wn * 4 + nf;
            int base = ((bfc * 16 + nt) * 2) * APITCH + lane;
            #pragma unroll
            for (int s = 0; s < 2; s++) {
                Bf [nf][s] = Bh[base + s * APITCH];
                Bfl[nf][s] = Bl[base + s * APITCH];
            }
        }
        #pragma unroll
        for (int mf = 0; mf < 2; mf++)
            #pragma unroll
            for (int nf = 0; nf < 4; nf++) {
                MMA16(acc[mf][nf], Af[mf],  Bf[nf]);
                MMA16(acc[mf][nf], Af[mf],  Bfl[nf]);
                MMA16(acc[mf][nf], Afl[mf], Bf[nf]);
            }
        __syncthreads();
    }

    #pragma unroll
    for (int mf = 0; mf < 2; mf++) {
        int row0 = m0 + wm * 32 + mf * 16 + lg;
        #pragma unroll
        for (int nf = 0; nf < 4; nf++) {
            int col = (wn * 4 + nf) * 8 + lt * 2;
            *(float2*)(Q + (size_t)row0 * YD + col)       = make_float2(acc[mf][nf][0], acc[mf][nf][1]);
            *(float2*)(Q + (size_t)(row0 + 8) * YD + col) = make_float2(acc[mf][nf][2], acc[mf][nf][3]);
        }
    }

    // ---- per-mtile last-arriver ticket: 16 blocks per mtile ----
    __threadfence();
    __syncthreads();
    if (tid == 0) {
        unsigned old = atomicAdd(&g_mt_ctr[mt], 1u);
        s_mt_last = (old == 15u);
        if (old == 15u) g_mt_ctr[mt] = 0u;   // safe: all 16 arrived
    }
    __syncthreads();
    if (!s_mt_last) return;

    // ---- rows phase for rows [m0, m0+64): R11 math verbatim ----
    {
        double* sSy  = (double*)SM;          // 128 doubles
        double* sSy2 = (double*)SM + 128;    // 128 doubles
        __threadfence();                     // acquire all blocks' Q writes
        if (tid < YD) {
            double s = 0.0, s2 = 0.0;
            #pragma unroll
            for (int p = 0; p < NPART; p++) { s += g_SyP[p][tid]; s2 += g_Sy2P[p][tid]; }
            sSy[tid] = s; sSy2[tid] = s2;
        }
        __syncthreads();

        // 8 warps x 8 rows each
        for (int r8 = 0; r8 < 8; r8++) {
            const int i = m0 + wid * 8 + r8;
            double pos = 0.0, row = 0.0;
            #pragma unroll
            for (int q = 0; q < 4; q++) {
                int d = q * 32 + lane;
                int idx = i * YD + d;
                float muf = b2mu[d];
                float sf  = b2lv[d];
                #pragma unroll
                for (int j = 0; j < KS2; j++) {
                    muf += g_Q[0][j][idx];
                    sf  += g_Q[1][j][idx];
                }
                float lvf = tanhf(sf);
                float ivf = expf(-lvf);
                float yf  = Y[idx];

                float dmy = muf - yf;
                pos += (double)fmaf(-0.5f * dmy * dmy, ivf, -0.5f * lvf);

                double mu = (double)muf;
                double tq = fma(mu, fma(512.0, mu, -2.0 * sSy[d]), sSy2[d]);
                row = fma(-0.5 * (double)ivf, tq, row);
                row = fma(-256.0, (double)lvf, row);
            }
            #pragma unroll
            for (int off = 16; off > 0; off >>= 1) {
                pos += __shfl_down_sync(0xffffffffu, pos, off);
                row += __shfl_down_sync(0xffffffffu, row, off);
            }
            if (lane == 0) {
                g_pos_row[i] = pos;
                g_all_row[i] = row;
            }
        }
    }

    // ---- global ticket: 8 mtile finishers ----
    __threadfence();
    __syncthreads();
    if (tid == 0) {
        unsigned old = atomicAdd(&g_ctr, 1u);
        s_last = (old == 7u);
        if (old == 7u) g_ctr = 0u;
    }
    __syncthreads();
    if (!s_last) return;

    // ---- final deterministic reduce over 512 rows (256 threads) ----
    {
        double* sp = (double*)SM;            // 256 doubles
        double* sa = (double*)SM + 256;      // 256 doubles
        __threadfence();
        double p0 = g_pos_row[tid] + g_pos_row[tid + 256];
        double a0 = g_all_row[tid] + g_all_row[tid + 256];
        __syncthreads();
        sp[tid] = p0;
        sa[tid] = a0;
        __syncthreads();
        #pragma unroll
        for (int s = 128; s > 0; s >>= 1) {
            if (tid < s) { sp[tid] += sp[tid + s]; sa[tid] += sa[tid + s]; }
            __syncthreads();
        }
        if (tid == 0)
            out[0] = (float)(sp[0] / 512.0 - sa[0] / (512.0 * 512.0));
        for (int k = tid + 1; k < out_size; k += 256) out[k] = 0.0f;
    }
}

// ---------------------------------------------------------------------------
extern "C" void kernel_launch(void* const* d_in, const int* in_sizes, int n_in,
                              void* d_out, int out_size)
{
    const float* x   = (const float*)d_in[0];
    const float* y   = (const float*)d_in[1];
    const float* w1m = (const float*)d_in[2];
    const float* b1m = (const float*)d_in[3];
    const float* w2m = (const float*)d_in[4];
    const float* b2m = (const float*)d_in[5];
    const float* w1l = (const float*)d_in[6];
    const float* b1l = (const float*)d_in[7];
    const float* w2l = (const float*)d_in[8];
    const float* b2l = (const float*)d_in[9];

    k_gemm1_mma<<<128 + NPART, 1024>>>(x, y, w1m, w1l);
    k_gemm2_rows<<<128, 256>>>(b1m, b1l, w2m, w2l, y, b2m, b2l,
                               (float*)d_out, out_size);
}